// round 5
// baseline (speedup 1.0000x reference)
#include <cuda_runtime.h>
#include <stdint.h>

typedef unsigned char u8;

#define Bn 16
#define Hn 512
#define Wn 512
#define HW (Hn * Wn)
#define Nn (Bn * HW)

// ---------------- scratch (device globals; no allocation) ----------------
__device__ u8  g_bufA[Nn];
__device__ u8  g_bufB[Nn];
__device__ u8  g_bufC[Nn];
__device__ int g_labels[Nn];
__device__ int g_sizes[Nn];
__device__ int g_ncomp[Bn];

// ---------------- union-find helpers ----------------
__device__ __forceinline__ int findroot(const int* L, int x) {
    int p = ((volatile const int*)L)[x];
    while (p != x) { x = p; p = ((volatile const int*)L)[x]; }
    return x;
}

__device__ __forceinline__ void unite(int* L, int a, int b) {
    while (true) {
        a = findroot(L, a);
        b = findroot(L, b);
        if (a == b) return;
        int mn = min(a, b), mx = max(a, b);
        int old = atomicMin(&L[mx], mn);
        if (old == mx) return;
        a = mn; b = old;
    }
}

// ---------------- CCL kernels ----------------
__global__ void k_thresh_init(const float* __restrict__ in, u8* __restrict__ fg,
                              int* __restrict__ L, int* __restrict__ S, int* __restrict__ NC) {
    int i = blockIdx.x * blockDim.x + threadIdx.x;
    if (i >= Nn) return;
    u8 f = (in[i] > 0.0f) ? 1 : 0;
    fg[i] = f;
    L[i] = f ? i : -1;
    S[i] = 0;
    if (i < Bn) NC[i] = 0;
}

__global__ void k_ccl_init(const u8* __restrict__ fg, int* __restrict__ L,
                           int* __restrict__ S, int* __restrict__ NC, int invert) {
    int i = blockIdx.x * blockDim.x + threadIdx.x;
    if (i >= Nn) return;
    int act = ((int)(fg[i] != 0)) ^ invert;
    L[i] = act ? i : -1;
    S[i] = 0;
    if (i < Bn) NC[i] = 0;
}

__global__ void k_merge(const u8* __restrict__ fg, int* __restrict__ L, int invert) {
    int i = blockIdx.x * blockDim.x + threadIdx.x;
    if (i >= Nn) return;
    if ((((int)(fg[i] != 0)) ^ invert) == 0) return;
    int x = i & (Wn - 1);
    int y = (i >> 9) & (Hn - 1);
    if (x > 0  && ((((int)(fg[i - 1]  != 0)) ^ invert) != 0)) unite(L, i, i - 1);
    if (y > 0  && ((((int)(fg[i - Wn] != 0)) ^ invert) != 0)) unite(L, i, i - Wn);
}

__global__ void k_flatten_count(const u8* __restrict__ fg, int* __restrict__ L,
                                int* __restrict__ S, int* __restrict__ NC, int invert) {
    int i = blockIdx.x * blockDim.x + threadIdx.x;
    if (i >= Nn) return;
    if ((((int)(fg[i] != 0)) ^ invert) == 0) return;
    int r = findroot(L, i);
    L[i] = r;
    int old = atomicAdd(&S[r], 1);
    if (old == 0) atomicAdd(&NC[i / HW], 1);
}

__global__ void k_filter_rso(u8* __restrict__ fg, const int* __restrict__ L,
                             const int* __restrict__ S, const int* __restrict__ NC,
                             int minsize) {
    int i = blockIdx.x * blockDim.x + threadIdx.x;
    if (i >= Nn) return;
    if (!fg[i]) return;
    if (NC[i / HW] <= 1) return;          // guard: only remove when >1 component
    if (S[L[i]] < minsize) fg[i] = 0;
}

__global__ void k_filter_holes(u8* __restrict__ fg, const int* __restrict__ L,
                               const int* __restrict__ S, int thresh) {
    int i = blockIdx.x * blockDim.x + threadIdx.x;
    if (i >= Nn) return;
    if (fg[i]) return;
    if (S[L[i]] < thresh) fg[i] = 1;      // fill small background component
}

// ---------------- morphology ----------------
// Erosion: OOB counts as foreground (skip). Dilation: OOB counts as background (skip).

__global__ void k_erode_r2(const u8* __restrict__ in, u8* __restrict__ out) {
    int x = blockIdx.x * blockDim.x + threadIdx.x;
    int y = blockIdx.y * blockDim.y + threadIdx.y;
    int b = blockIdx.z;
    const u8* img = in + b * HW;
    const int wx[3] = {2, 1, 0};          // disk(2) half-widths per |dy|
    u8 res = 1;
    #pragma unroll
    for (int dy = -2; dy <= 2; ++dy) {
        int yy = y + dy;
        if (yy < 0 || yy >= Hn) continue;
        int w = wx[dy < 0 ? -dy : dy];
        int lo = max(x - w, 0), hi = min(x + w, Wn - 1);
        const u8* row = img + yy * Wn;
        for (int xx = lo; xx <= hi; ++xx) res &= row[xx];
        if (!res) break;
    }
    out[b * HW + y * Wn + x] = res;
}

// horizontal erosions width 3/4/5 packed into bits 0/1/2
__global__ void k_herode5(const u8* __restrict__ in, u8* __restrict__ out) {
    int x = blockIdx.x * blockDim.x + threadIdx.x;
    int y = blockIdx.y * blockDim.y + threadIdx.y;
    int b = blockIdx.z;
    const u8* row = in + b * HW + y * Wn;
    u8 e3 = 1;
    int lo = max(x - 3, 0), hi = min(x + 3, Wn - 1);
    for (int xx = lo; xx <= hi; ++xx) e3 &= row[xx];
    u8 e4 = e3;
    if (x >= 4)      e4 &= row[x - 4];
    if (x + 4 < Wn)  e4 &= row[x + 4];
    u8 e5 = e4;
    if (x >= 5)      e5 &= row[x - 5];
    if (x + 5 < Wn)  e5 &= row[x + 5];
    out[b * HW + y * Wn + x] = (u8)(e3 | (e4 << 1) | (e5 << 2));
}

__global__ void k_verode5(const u8* __restrict__ packed, const u8* __restrict__ orig,
                          u8* __restrict__ out) {
    int x = blockIdx.x * blockDim.x + threadIdx.x;
    int y = blockIdx.y * blockDim.y + threadIdx.y;
    int b = blockIdx.z;
    // |dy|: 0 -> width5(bit2), 1..3 -> width4(bit1), 4 -> width3(bit0), 5 -> width0(orig)
    const int bitsel[5] = {2, 1, 1, 1, 0};
    u8 res = 1;
    #pragma unroll
    for (int dy = -5; dy <= 5; ++dy) {
        int yy = y + dy;
        if (yy < 0 || yy >= Hn) continue;
        int ad = dy < 0 ? -dy : dy;
        int off = b * HW + yy * Wn + x;
        u8 v = (ad == 5) ? orig[off] : (u8)((packed[off] >> bitsel[ad]) & 1);
        res &= v;
        if (!res) break;
    }
    out[b * HW + y * Wn + x] = res;
}

__global__ void k_hdilate5(const u8* __restrict__ in, u8* __restrict__ out) {
    int x = blockIdx.x * blockDim.x + threadIdx.x;
    int y = blockIdx.y * blockDim.y + threadIdx.y;
    int b = blockIdx.z;
    const u8* row = in + b * HW + y * Wn;
    u8 d3 = 0;
    int lo = max(x - 3, 0), hi = min(x + 3, Wn - 1);
    for (int xx = lo; xx <= hi; ++xx) d3 |= row[xx];
    u8 d4 = d3;
    if (x >= 4)      d4 |= row[x - 4];
    if (x + 4 < Wn)  d4 |= row[x + 4];
    u8 d5 = d4;
    if (x >= 5)      d5 |= row[x - 5];
    if (x + 5 < Wn)  d5 |= row[x + 5];
    out[b * HW + y * Wn + x] = (u8)((d3 != 0) | ((d4 != 0) << 1) | ((d5 != 0) << 2));
}

__global__ void k_vdilate5(const u8* __restrict__ packed, const u8* __restrict__ orig,
                           u8* __restrict__ out) {
    int x = blockIdx.x * blockDim.x + threadIdx.x;
    int y = blockIdx.y * blockDim.y + threadIdx.y;
    int b = blockIdx.z;
    const int bitsel[5] = {2, 1, 1, 1, 0};
    u8 res = 0;
    #pragma unroll
    for (int dy = -5; dy <= 5; ++dy) {
        int yy = y + dy;
        if (yy < 0 || yy >= Hn) continue;
        int ad = dy < 0 ? -dy : dy;
        int off = b * HW + yy * Wn + x;
        u8 v = (ad == 5) ? orig[off] : (u8)((packed[off] >> bitsel[ad]) & 1);
        res |= v;
        if (res) break;
    }
    out[b * HW + y * Wn + x] = res ? 1 : 0;
}

// final dilate with disk(1) (plus-shape) fused with float output
__global__ void k_dilate1_out(const u8* __restrict__ in, float* __restrict__ out) {
    int x = blockIdx.x * blockDim.x + threadIdx.x;
    int y = blockIdx.y * blockDim.y + threadIdx.y;
    int b = blockIdx.z;
    const u8* img = in + b * HW;
    u8 res = img[y * Wn + x];
    if (x > 0)      res |= img[y * Wn + x - 1];
    if (x < Wn - 1) res |= img[y * Wn + x + 1];
    if (y > 0)      res |= img[(y - 1) * Wn + x];
    if (y < Hn - 1) res |= img[(y + 1) * Wn + x];
    out[b * HW + y * Wn + x] = res ? 1.0f : 0.0f;
}

// ---------------- launch ----------------
extern "C" void kernel_launch(void* const* d_in, const int* in_sizes, int n_in,
                              void* d_out, int out_size) {
    const float* in = (const float*)d_in[0];
    float* out = (float*)d_out;

    void *pA, *pB, *pC, *pL, *pS, *pN;
    cudaGetSymbolAddress(&pA, g_bufA);
    cudaGetSymbolAddress(&pB, g_bufB);
    cudaGetSymbolAddress(&pC, g_bufC);
    cudaGetSymbolAddress(&pL, g_labels);
    cudaGetSymbolAddress(&pS, g_sizes);
    cudaGetSymbolAddress(&pN, g_ncomp);
    u8*  A  = (u8*)pA;
    u8*  Bb = (u8*)pB;
    u8*  C  = (u8*)pC;
    int* L  = (int*)pL;
    int* S  = (int*)pS;
    int* NC = (int*)pN;

    const int T = 256;
    const int G = (Nn + T - 1) / T;
    dim3 mb(32, 8, 1);
    dim3 mg(Wn / 32, Hn / 8, Bn);

    // fg = input > 0
    k_thresh_init<<<G, T>>>(in, A, L, S, NC);

    // remove_small_objects(fg, 2000, guard)
    k_merge<<<G, T>>>(A, L, 0);
    k_flatten_count<<<G, T>>>(A, L, S, NC, 0);
    k_filter_rso<<<G, T>>>(A, L, S, NC, 2000);

    // fill small holes: label background, fill comps with size < 301
    k_ccl_init<<<G, T>>>(A, L, S, NC, 1);
    k_merge<<<G, T>>>(A, L, 1);
    k_flatten_count<<<G, T>>>(A, L, S, NC, 1);
    k_filter_holes<<<G, T>>>(A, L, S, 301);

    // erode disk(2)
    k_erode_r2<<<mg, mb>>>(A, Bb);
    // opening with disk(5): erode then dilate (separated h/v passes)
    k_herode5<<<mg, mb>>>(Bb, C);
    k_verode5<<<mg, mb>>>(C, Bb, A);
    k_hdilate5<<<mg, mb>>>(A, C);
    k_vdilate5<<<mg, mb>>>(C, A, Bb);

    // remove_small_objects(fg, 2000, guard)
    k_ccl_init<<<G, T>>>(Bb, L, S, NC, 0);
    k_merge<<<G, T>>>(Bb, L, 0);
    k_flatten_count<<<G, T>>>(Bb, L, S, NC, 0);
    k_filter_rso<<<G, T>>>(Bb, L, S, NC, 2000);

    // dilate disk(1) + float output
    k_dilate1_out<<<mg, mb>>>(Bb, out);
}

// round 10
// speedup vs baseline: 5.4873x; 5.4873x over previous
#include <cuda_runtime.h>
#include <stdint.h>

typedef unsigned char u8;

#define Bn 16
#define Hn 512
#define Wn 512
#define HW (Hn * Wn)
#define Nn (Bn * HW)

// ---------------- scratch (device globals; no allocation) ----------------
__device__ u8  g_bufA[Nn];
__device__ u8  g_bufB[Nn];
__device__ u8  g_bufC[Nn];
__device__ int g_labels[Nn];
__device__ int g_sizes[Nn];
__device__ int g_ncomp[Bn];

// ---------------- union-find helpers ----------------
__device__ __forceinline__ int findroot(const int* L, int x) {
    int p = ((volatile const int*)L)[x];
    while (p != x) { x = p; p = ((volatile const int*)L)[x]; }
    return x;
}

__device__ __forceinline__ void unite(int* L, int a, int b) {
    while (true) {
        a = findroot(L, a);
        b = findroot(L, b);
        if (a == b) return;
        int mn = min(a, b), mx = max(a, b);
        int old = atomicMin(&L[mx], mn);
        if (old == mx) return;
        a = mn; b = old;
    }
}

// ---------------- CCL kernels ----------------
__global__ void k_thresh(const float* __restrict__ in, u8* __restrict__ fg) {
    int i = blockIdx.x * blockDim.x + threadIdx.x;
    fg[i] = (in[i] > 0.0f) ? 1 : 0;
}

// Per-row run-start labeling via shared-memory pointer jumping.
// Block = one row (512 threads). L[i] = index of start of this pixel's
// horizontal run (within-row segmented min), or -1 for inactive pixels.
__global__ void k_init_runs(const u8* __restrict__ fg, int* __restrict__ L,
                            int* __restrict__ S, int* __restrict__ NC, int invert) {
    __shared__ u8    a[Wn];
    __shared__ short ptr[Wn];
    int x = threadIdx.x;
    int y = blockIdx.x;
    int b = blockIdx.y;
    int rowbase = b * HW + y * Wn;
    int i = rowbase + x;
    int act = ((int)(fg[i] != 0)) ^ invert;
    a[x] = (u8)act;
    __syncthreads();
    short p = (act && x > 0 && a[x - 1]) ? (short)(x - 1) : (short)x;
    ptr[x] = p;
    __syncthreads();
    #pragma unroll
    for (int d = 0; d < 9; ++d) {
        short q = ptr[ptr[x]];
        __syncthreads();
        ptr[x] = q;
        __syncthreads();
    }
    L[i] = act ? (rowbase + (int)ptr[x]) : -1;
    S[i] = 0;
    if (y == 0 && x == 0) NC[b] = 0;
}

// Vertical unions only, one per run-overlap segment (leftmost pixel of overlap).
__global__ void k_merge_v(const u8* __restrict__ fg, int* __restrict__ L, int invert) {
    int i = blockIdx.x * blockDim.x + threadIdx.x;
    int x = i & (Wn - 1);
    int y = (i >> 9) & (Hn - 1);
    if (y == 0) return;
    int act = ((int)(fg[i] != 0)) ^ invert;
    if (!act) return;
    int up = ((int)(fg[i - Wn] != 0)) ^ invert;
    if (!up) return;
    // skip if left pixel would already have issued the same (run,run) union
    if (x > 0) {
        int lft = ((int)(fg[i - 1] != 0)) ^ invert;
        int upl = ((int)(fg[i - Wn - 1] != 0)) ^ invert;
        if (lft && upl) return;
    }
    unite(L, i, i - Wn);
}

// Flatten + warp-aggregated size counting + root-based component counting.
__global__ void k_flatten_count(const u8* __restrict__ fg, int* __restrict__ L,
                                int* __restrict__ S, int* __restrict__ NC, int invert) {
    int i = blockIdx.x * blockDim.x + threadIdx.x;
    int act = ((int)(fg[i] != 0)) ^ invert;
    int r = -1;
    if (act) {
        r = findroot(L, i);
        L[i] = r;
    }
    // warp-aggregate equal roots: one atomic per (warp, root)
    unsigned grp = __match_any_sync(0xffffffffu, r);
    int lane = threadIdx.x & 31;
    int leader = __ffs(grp) - 1;
    if (act && lane == leader) atomicAdd(&S[r], __popc(grp));
    // count components = count roots (r == i), ballot-aggregated
    unsigned rootmask = __ballot_sync(0xffffffffu, act && r == i);
    if (lane == 0 && rootmask) atomicAdd(&NC[i / HW], __popc(rootmask));
}

__global__ void k_filter_rso(u8* __restrict__ fg, const int* __restrict__ L,
                             const int* __restrict__ S, const int* __restrict__ NC,
                             int minsize) {
    int i = blockIdx.x * blockDim.x + threadIdx.x;
    if (!fg[i]) return;
    if (NC[i / HW] <= 1) return;          // guard: only remove when >1 component
    if (S[L[i]] < minsize) fg[i] = 0;
}

__global__ void k_filter_holes(u8* __restrict__ fg, const int* __restrict__ L,
                               const int* __restrict__ S, int thresh) {
    int i = blockIdx.x * blockDim.x + threadIdx.x;
    if (fg[i]) return;
    if (S[L[i]] < thresh) fg[i] = 1;      // fill small background component
}

// ---------------- morphology ----------------
// Erosion: OOB counts as foreground (skip). Dilation: OOB counts as background (skip).

__global__ void k_erode_r2(const u8* __restrict__ in, u8* __restrict__ out) {
    int x = blockIdx.x * blockDim.x + threadIdx.x;
    int y = blockIdx.y * blockDim.y + threadIdx.y;
    int b = blockIdx.z;
    const u8* img = in + b * HW;
    const int wx[3] = {2, 1, 0};          // disk(2) half-widths per |dy|
    u8 res = 1;
    #pragma unroll
    for (int dy = -2; dy <= 2; ++dy) {
        int yy = y + dy;
        if (yy < 0 || yy >= Hn) continue;
        int w = wx[dy < 0 ? -dy : dy];
        int lo = max(x - w, 0), hi = min(x + w, Wn - 1);
        const u8* row = img + yy * Wn;
        for (int xx = lo; xx <= hi; ++xx) res &= row[xx];
        if (!res) break;
    }
    out[b * HW + y * Wn + x] = res;
}

// horizontal erosions width 3/4/5 packed into bits 0/1/2
__global__ void k_herode5(const u8* __restrict__ in, u8* __restrict__ out) {
    int x = blockIdx.x * blockDim.x + threadIdx.x;
    int y = blockIdx.y * blockDim.y + threadIdx.y;
    int b = blockIdx.z;
    const u8* row = in + b * HW + y * Wn;
    u8 e3 = 1;
    int lo = max(x - 3, 0), hi = min(x + 3, Wn - 1);
    for (int xx = lo; xx <= hi; ++xx) e3 &= row[xx];
    u8 e4 = e3;
    if (x >= 4)      e4 &= row[x - 4];
    if (x + 4 < Wn)  e4 &= row[x + 4];
    u8 e5 = e4;
    if (x >= 5)      e5 &= row[x - 5];
    if (x + 5 < Wn)  e5 &= row[x + 5];
    out[b * HW + y * Wn + x] = (u8)(e3 | (e4 << 1) | (e5 << 2));
}

__global__ void k_verode5(const u8* __restrict__ packed, const u8* __restrict__ orig,
                          u8* __restrict__ out) {
    int x = blockIdx.x * blockDim.x + threadIdx.x;
    int y = blockIdx.y * blockDim.y + threadIdx.y;
    int b = blockIdx.z;
    // |dy|: 0 -> width5(bit2), 1..3 -> width4(bit1), 4 -> width3(bit0), 5 -> orig
    const int bitsel[5] = {2, 1, 1, 1, 0};
    u8 res = 1;
    #pragma unroll
    for (int dy = -5; dy <= 5; ++dy) {
        int yy = y + dy;
        if (yy < 0 || yy >= Hn) continue;
        int ad = dy < 0 ? -dy : dy;
        int off = b * HW + yy * Wn + x;
        u8 v = (ad == 5) ? orig[off] : (u8)((packed[off] >> bitsel[ad]) & 1);
        res &= v;
        if (!res) break;
    }
    out[b * HW + y * Wn + x] = res;
}

__global__ void k_hdilate5(const u8* __restrict__ in, u8* __restrict__ out) {
    int x = blockIdx.x * blockDim.x + threadIdx.x;
    int y = blockIdx.y * blockDim.y + threadIdx.y;
    int b = blockIdx.z;
    const u8* row = in + b * HW + y * Wn;
    u8 d3 = 0;
    int lo = max(x - 3, 0), hi = min(x + 3, Wn - 1);
    for (int xx = lo; xx <= hi; ++xx) d3 |= row[xx];
    u8 d4 = d3;
    if (x >= 4)      d4 |= row[x - 4];
    if (x + 4 < Wn)  d4 |= row[x + 4];
    u8 d5 = d4;
    if (x >= 5)      d5 |= row[x - 5];
    if (x + 5 < Wn)  d5 |= row[x + 5];
    out[b * HW + y * Wn + x] = (u8)((d3 != 0) | ((d4 != 0) << 1) | ((d5 != 0) << 2));
}

__global__ void k_vdilate5(const u8* __restrict__ packed, const u8* __restrict__ orig,
                           u8* __restrict__ out) {
    int x = blockIdx.x * blockDim.x + threadIdx.x;
    int y = blockIdx.y * blockDim.y + threadIdx.y;
    int b = blockIdx.z;
    const int bitsel[5] = {2, 1, 1, 1, 0};
    u8 res = 0;
    #pragma unroll
    for (int dy = -5; dy <= 5; ++dy) {
        int yy = y + dy;
        if (yy < 0 || yy >= Hn) continue;
        int ad = dy < 0 ? -dy : dy;
        int off = b * HW + yy * Wn + x;
        u8 v = (ad == 5) ? orig[off] : (u8)((packed[off] >> bitsel[ad]) & 1);
        res |= v;
        if (res) break;
    }
    out[b * HW + y * Wn + x] = res ? 1 : 0;
}

// final dilate with disk(1) (plus-shape) fused with float output
__global__ void k_dilate1_out(const u8* __restrict__ in, float* __restrict__ out) {
    int x = blockIdx.x * blockDim.x + threadIdx.x;
    int y = blockIdx.y * blockDim.y + threadIdx.y;
    int b = blockIdx.z;
    const u8* img = in + b * HW;
    u8 res = img[y * Wn + x];
    if (x > 0)      res |= img[y * Wn + x - 1];
    if (x < Wn - 1) res |= img[y * Wn + x + 1];
    if (y > 0)      res |= img[(y - 1) * Wn + x];
    if (y < Hn - 1) res |= img[(y + 1) * Wn + x];
    out[b * HW + y * Wn + x] = res ? 1.0f : 0.0f;
}

// ---------------- launch ----------------
extern "C" void kernel_launch(void* const* d_in, const int* in_sizes, int n_in,
                              void* d_out, int out_size) {
    const float* in = (const float*)d_in[0];
    float* out = (float*)d_out;

    void *pA, *pB, *pC, *pL, *pS, *pN;
    cudaGetSymbolAddress(&pA, g_bufA);
    cudaGetSymbolAddress(&pB, g_bufB);
    cudaGetSymbolAddress(&pC, g_bufC);
    cudaGetSymbolAddress(&pL, g_labels);
    cudaGetSymbolAddress(&pS, g_sizes);
    cudaGetSymbolAddress(&pN, g_ncomp);
    u8*  A  = (u8*)pA;
    u8*  Bb = (u8*)pB;
    u8*  C  = (u8*)pC;
    int* L  = (int*)pL;
    int* S  = (int*)pS;
    int* NC = (int*)pN;

    const int T = 256;
    const int G = Nn / T;
    dim3 rg(Hn, Bn, 1);        // run-init: one block per row
    dim3 mb(32, 8, 1);
    dim3 mg(Wn / 32, Hn / 8, Bn);

    // fg = input > 0
    k_thresh<<<G, T>>>(in, A);

    // remove_small_objects(fg, 2000, guard)
    k_init_runs<<<rg, Wn>>>(A, L, S, NC, 0);
    k_merge_v<<<G, T>>>(A, L, 0);
    k_flatten_count<<<G, T>>>(A, L, S, NC, 0);
    k_filter_rso<<<G, T>>>(A, L, S, NC, 2000);

    // fill small holes: label background, fill comps with size < 301
    k_init_runs<<<rg, Wn>>>(A, L, S, NC, 1);
    k_merge_v<<<G, T>>>(A, L, 1);
    k_flatten_count<<<G, T>>>(A, L, S, NC, 1);
    k_filter_holes<<<G, T>>>(A, L, S, 301);

    // erode disk(2)
    k_erode_r2<<<mg, mb>>>(A, Bb);
    // opening with disk(5): erode then dilate (separated h/v passes)
    k_herode5<<<mg, mb>>>(Bb, C);
    k_verode5<<<mg, mb>>>(C, Bb, A);
    k_hdilate5<<<mg, mb>>>(A, C);
    k_vdilate5<<<mg, mb>>>(C, A, Bb);

    // remove_small_objects(fg, 2000, guard)
    k_init_runs<<<rg, Wn>>>(Bb, L, S, NC, 0);
    k_merge_v<<<G, T>>>(Bb, L, 0);
    k_flatten_count<<<G, T>>>(Bb, L, S, NC, 0);
    k_filter_rso<<<G, T>>>(Bb, L, S, NC, 2000);

    // dilate disk(1) + float output
    k_dilate1_out<<<mg, mb>>>(Bb, out);
}

// round 12
// speedup vs baseline: 10.4716x; 1.9084x over previous
#include <cuda_runtime.h>
#include <stdint.h>

typedef uint32_t u32;

#define Bn 16
#define Hn 512
#define Wn 512
#define HW (Hn * Wn)
#define Nn (Bn * HW)
#define WPR 16                    // 32-bit words per row
#define TOTW (Bn * Hn * WPR)

// ---------------- scratch (device globals; no allocation) ----------------
__device__ u32 g_mA[TOTW];
__device__ u32 g_mB[TOTW];
__device__ u32 g_mC[TOTW];
__device__ int g_L[Nn];           // union-find labels (per pixel; runs share run-start)
__device__ int g_RL[Nn];          // run length, valid at run-start indices
__device__ int g_SA[Nn];          // component sizes (CCL1 / CCL3)
__device__ int g_SB[Nn];          // component sizes (CCL2)
__device__ int g_NC[2 * Bn];      // component counts per image, two banks

// ---------------- union-find ----------------
// READ-ONLY chase. No path-halving writes: a plain store here can race with
// unite's atomicMin link installation and silently lose a union.
__device__ __forceinline__ int findroot(const int* L, int x) {
    int p = ((volatile const int*)L)[x];
    while (p != x) { x = p; p = ((volatile const int*)L)[x]; }
    return x;
}

__device__ __forceinline__ void unite(int* L, int a, int b) {
    while (true) {
        a = findroot(L, a);
        b = findroot(L, b);
        if (a == b) return;
        int mn = min(a, b), mx = max(a, b);
        int old = atomicMin(&L[mx], mn);
        if (old == mx) return;
        a = mn; b = old;
    }
}

// ---------------- row-local run init (block = one row, 512 threads) ------
// shw[16] holds the row's mask words; inv XORs them (0 or ~0).
// Writes: L[i] = run-start index (active px only); at run starts: RL and S=0.
__device__ __forceinline__ void run_init_row(const u32* shw, u32 inv,
                                             int b, int y, int x,
                                             int* L, int* RL, int* S) {
    int warp = x >> 5, lane = x & 31;
    u32 bwd = shw[warp] ^ inv;
    int act = (bwd >> lane) & 1;
    if (!act) return;
    int rowbase = b * HW + y * Wn;
    // run start: nearest inactive strictly below x, +1
    int rs;
    u32 z = ~bwd & ((lane == 0) ? 0u : ((1u << lane) - 1u));
    if (z) {
        rs = (x & ~31) + (31 - __clz(z)) + 1;
    } else {
        int wq = warp - 1;
        while (wq >= 0 && (shw[wq] ^ inv) == 0xffffffffu) wq--;
        if (wq < 0) rs = 0;
        else rs = wq * 32 + (31 - __clz(~(shw[wq] ^ inv))) + 1;
    }
    int gi = rowbase + x;
    L[gi] = rowbase + rs;
    if (x == rs) {
        // run end: first inactive strictly above x
        int re;
        u32 z2 = ~bwd & ~((2u << lane) - 1u);
        if (z2) {
            re = (x & ~31) + __ffs(z2) - 1;
        } else {
            int wq = warp + 1;
            while (wq < WPR && (shw[wq] ^ inv) == 0xffffffffu) wq++;
            if (wq >= WPR) re = Wn;
            else re = wq * 32 + __ffs(~(shw[wq] ^ inv)) - 1;
        }
        RL[gi] = re - x;
        S[gi] = 0;                // zero the size slot at every potential root
    }
}

// ---------------- kernels ----------------

// threshold + CCL1 run init (fused). grid (Hn, Bn), block 512.
__global__ void k_thresh_init(const float* __restrict__ in, u32* __restrict__ mask,
                              int* __restrict__ L, int* __restrict__ RL,
                              int* __restrict__ S, int* __restrict__ NC) {
    __shared__ u32 shw[WPR];
    int x = threadIdx.x, y = blockIdx.x, b = blockIdx.y;
    int warp = x >> 5, lane = x & 31;
    float v = in[b * HW + y * Wn + x];
    u32 bal = __ballot_sync(0xffffffffu, v > 0.0f);
    if (lane == 0) {
        shw[warp] = bal;
        mask[(b * Hn + y) * WPR + warp] = bal;
    }
    __syncthreads();
    run_init_row(shw, 0u, b, y, x, L, RL, S);
    if (x == 0 && y == 0) NC[b] = 0;
}

// generic run init from a mask (CCL3). grid (Hn, Bn), block 512.
__global__ void k_init_mask(const u32* __restrict__ mask,
                            int* __restrict__ L, int* __restrict__ RL,
                            int* __restrict__ S, int* __restrict__ NC) {
    __shared__ u32 shw[WPR];
    int x = threadIdx.x, y = blockIdx.x, b = blockIdx.y;
    if ((x & 31) == 0) shw[x >> 5] = mask[(b * Hn + y) * WPR + (x >> 5)];
    __syncthreads();
    run_init_row(shw, 0u, b, y, x, L, RL, S);
    if (x == 0 && y == 0) NC[b] = 0;
}

// vertical unions, one per run-overlap segment. thread per word.
__global__ void k_merge(const u32* __restrict__ mask, int* __restrict__ L, u32 inv) {
    int id = blockIdx.x * blockDim.x + threadIdx.x;
    int w = id & (WPR - 1);
    int y = (id >> 4) & (Hn - 1);
    int b = id >> 13;
    if (y == 0) return;
    u32 cur = mask[id] ^ inv;
    u32 up  = mask[id - WPR] ^ inv;
    u32 m = cur & up;
    if (!m) return;
    u32 carry = 0;
    if (w > 0) {
        u32 curp = mask[id - 1] ^ inv;
        u32 upp  = mask[id - WPR - 1] ^ inv;
        carry = (curp & upp) >> 31;
    }
    u32 starts = m & ~((m << 1) | carry);
    int base = b * HW + y * Wn + w * 32;
    while (starts) {
        int p = __ffs(starts) - 1;
        starts &= starts - 1;
        unite(L, base + p, base + p - Wn);
    }
}

// flatten run-starts, accumulate run lengths into root sizes, count roots.
__global__ void k_flatten(const u32* __restrict__ mask, int* __restrict__ L,
                          const int* __restrict__ RL, int* __restrict__ S,
                          int* __restrict__ NC, u32 inv) {
    int id = blockIdx.x * blockDim.x + threadIdx.x;
    int w = id & (WPR - 1);
    int y = (id >> 4) & (Hn - 1);
    int b = id >> 13;
    u32 bwd = mask[id] ^ inv;
    if (!bwd) return;
    u32 carry = (w > 0) ? ((mask[id - 1] ^ inv) >> 31) : 0;
    u32 starts = bwd & ~((bwd << 1) | carry);
    int base = b * HW + y * Wn + w * 32;
    int nroots = 0;
    while (starts) {
        int p = __ffs(starts) - 1;
        starts &= starts - 1;
        int i = base + p;
        int r = findroot(L, i);
        L[i] = r;                 // written exactly once, by this thread only
        atomicAdd(&S[r], RL[i]);
        if (r == i) nroots++;
    }
    if (nroots) atomicAdd(&NC[b], nroots);
}

// remove_small_objects filter (in-place mask) + fused CCL2 (background) init.
// All label reads are row-local (run-start trick), ordered before L overwrites.
__global__ void k_filter_rso_init2(u32* __restrict__ mask,
                                   int* __restrict__ L, int* __restrict__ RL,
                                   const int* __restrict__ S_rd, int* __restrict__ S_wr,
                                   const int* __restrict__ NC_rd, int* __restrict__ NC_wr,
                                   int minsize) {
    __shared__ u32 shw[WPR];
    int x = threadIdx.x, y = blockIdx.x, b = blockIdx.y;
    int warp = x >> 5, lane = x & 31;
    int widx = (b * Hn + y) * WPR + warp;
    if (lane == 0) shw[warp] = mask[widx];
    __syncthreads();
    u32 wd = shw[warp];
    int act = (wd >> lane) & 1;
    int i = b * HW + y * Wn + x;
    int keep = act;
    if (act && NC_rd[b] > 1) {
        int prevbit = (lane > 0) ? ((wd >> (lane - 1)) & 1)
                                 : ((warp > 0) ? ((shw[warp - 1] >> 31) & 1) : 0);
        int r = prevbit ? L[L[i]] : L[i];   // row-local reads only
        if (S_rd[r] < minsize) keep = 0;
    }
    u32 bal = __ballot_sync(0xffffffffu, keep);
    __syncthreads();                        // all CCL1 label reads done
    if (lane == 0) { shw[warp] = bal; mask[widx] = bal; }
    __syncthreads();
    run_init_row(shw, 0xffffffffu, b, y, x, L, RL, S_wr);   // background runs
    if (x == 0 && y == 0) NC_wr[b] = 0;
}

// fill small background components (in-place mask).
__global__ void k_filter_holes(u32* __restrict__ mask, const int* __restrict__ L,
                               const int* __restrict__ S, int thresh) {
    __shared__ u32 shw[WPR];
    int x = threadIdx.x, y = blockIdx.x, b = blockIdx.y;
    int warp = x >> 5, lane = x & 31;
    int widx = (b * Hn + y) * WPR + warp;
    if (lane == 0) shw[warp] = mask[widx];
    __syncthreads();
    u32 wd = shw[warp];
    int bit = (wd >> lane) & 1;
    int res = bit;
    if (!bit) {
        int i = b * HW + y * Wn + x;
        int r = L[L[i]];
        if (S[r] < thresh) res = 1;
    }
    u32 bal = __ballot_sync(0xffffffffu, res);
    if (lane == 0) mask[widx] = bal;
}

// standalone RSO filter (CCL3), in-place mask.
__global__ void k_filter_rso(u32* __restrict__ mask, const int* __restrict__ L,
                             const int* __restrict__ S, const int* __restrict__ NC,
                             int minsize) {
    __shared__ u32 shw[WPR];
    int x = threadIdx.x, y = blockIdx.x, b = blockIdx.y;
    int warp = x >> 5, lane = x & 31;
    int widx = (b * Hn + y) * WPR + warp;
    if (lane == 0) shw[warp] = mask[widx];
    __syncthreads();
    u32 wd = shw[warp];
    int act = (wd >> lane) & 1;
    int keep = act;
    if (act && NC[b] > 1) {
        int i = b * HW + y * Wn + x;
        int r = L[L[i]];
        if (S[r] < minsize) keep = 0;
    }
    u32 bal = __ballot_sync(0xffffffffu, keep);
    if (lane == 0) mask[widx] = bal;
}

// ---------------- bitwise morphology ----------------
// Erosion OOB = 1, dilation OOB = 0. Bit p of word w = pixel x = 32w + p.

template<int W>
__device__ __forceinline__ u32 h_erode(const u32* __restrict__ m, int rowidx, int w) {
    u32 c = m[rowidx + w];
    if (W == 0) return c;
    u32 l = (w > 0) ? m[rowidx + w - 1] : 0xffffffffu;
    u32 r = (w < WPR - 1) ? m[rowidx + w + 1] : 0xffffffffu;
    u32 e = c;
#pragma unroll
    for (int k = 1; k <= W; k++) {
        e &= (c >> k) | (r << (32 - k));
        e &= (c << k) | (l >> (32 - k));
    }
    return e;
}

template<int W>
__device__ __forceinline__ u32 h_dilate(const u32* __restrict__ m, int rowidx, int w) {
    u32 c = m[rowidx + w];
    if (W == 0) return c;
    u32 l = (w > 0) ? m[rowidx + w - 1] : 0u;
    u32 r = (w < WPR - 1) ? m[rowidx + w + 1] : 0u;
    u32 d = c;
#pragma unroll
    for (int k = 1; k <= W; k++) {
        d |= (c >> k) | (r << (32 - k));
        d |= (c << k) | (l >> (32 - k));
    }
    return d;
}

// disk(2): widths per |dy| = {2,1,0}
__global__ void k_erode_r2(const u32* __restrict__ in, u32* __restrict__ out) {
    int id = blockIdx.x * blockDim.x + threadIdx.x;
    int w = id & (WPR - 1);
    int y = (id >> 4) & (Hn - 1);
    int rbase = (id >> 4) - y;            // (b*Hn) row-index base
    u32 res = h_erode<2>(in, (rbase + y) * WPR, w);
    if (y >= 1)      res &= h_erode<1>(in, (rbase + y - 1) * WPR, w);
    if (y <= Hn - 2) res &= h_erode<1>(in, (rbase + y + 1) * WPR, w);
    if (y >= 2)      res &= h_erode<0>(in, (rbase + y - 2) * WPR, w);
    if (y <= Hn - 3) res &= h_erode<0>(in, (rbase + y + 2) * WPR, w);
    out[id] = res;
}

// disk(5): widths per |dy| = {5,4,4,4,3,0}
__global__ void k_erode_r5(const u32* __restrict__ in, u32* __restrict__ out) {
    int id = blockIdx.x * blockDim.x + threadIdx.x;
    int w = id & (WPR - 1);
    int y = (id >> 4) & (Hn - 1);
    int rbase = (id >> 4) - y;
    u32 res = h_erode<5>(in, (rbase + y) * WPR, w);
    if (y >= 1)      res &= h_erode<4>(in, (rbase + y - 1) * WPR, w);
    if (y <= Hn - 2) res &= h_erode<4>(in, (rbase + y + 1) * WPR, w);
    if (y >= 2)      res &= h_erode<4>(in, (rbase + y - 2) * WPR, w);
    if (y <= Hn - 3) res &= h_erode<4>(in, (rbase + y + 2) * WPR, w);
    if (y >= 3)      res &= h_erode<4>(in, (rbase + y - 3) * WPR, w);
    if (y <= Hn - 4) res &= h_erode<4>(in, (rbase + y + 3) * WPR, w);
    if (y >= 4)      res &= h_erode<3>(in, (rbase + y - 4) * WPR, w);
    if (y <= Hn - 5) res &= h_erode<3>(in, (rbase + y + 4) * WPR, w);
    if (y >= 5)      res &= h_erode<0>(in, (rbase + y - 5) * WPR, w);
    if (y <= Hn - 6) res &= h_erode<0>(in, (rbase + y + 5) * WPR, w);
    out[id] = res;
}

__global__ void k_dilate_r5(const u32* __restrict__ in, u32* __restrict__ out) {
    int id = blockIdx.x * blockDim.x + threadIdx.x;
    int w = id & (WPR - 1);
    int y = (id >> 4) & (Hn - 1);
    int rbase = (id >> 4) - y;
    u32 res = h_dilate<5>(in, (rbase + y) * WPR, w);
    if (y >= 1)      res |= h_dilate<4>(in, (rbase + y - 1) * WPR, w);
    if (y <= Hn - 2) res |= h_dilate<4>(in, (rbase + y + 1) * WPR, w);
    if (y >= 2)      res |= h_dilate<4>(in, (rbase + y - 2) * WPR, w);
    if (y <= Hn - 3) res |= h_dilate<4>(in, (rbase + y + 2) * WPR, w);
    if (y >= 3)      res |= h_dilate<4>(in, (rbase + y - 3) * WPR, w);
    if (y <= Hn - 4) res |= h_dilate<4>(in, (rbase + y + 3) * WPR, w);
    if (y >= 4)      res |= h_dilate<3>(in, (rbase + y - 4) * WPR, w);
    if (y <= Hn - 5) res |= h_dilate<3>(in, (rbase + y + 4) * WPR, w);
    if (y >= 5)      res |= h_dilate<0>(in, (rbase + y - 5) * WPR, w);
    if (y <= Hn - 6) res |= h_dilate<0>(in, (rbase + y + 5) * WPR, w);
    out[id] = res;
}

// final disk(1) dilation fused with float output.
__global__ void k_dilate1_out(const u32* __restrict__ mask, float* __restrict__ out) {
    int x = blockIdx.x * 32 + threadIdx.x;
    int y = blockIdx.y * 8 + threadIdx.y;
    int b = blockIdx.z;
    int w = x >> 5, lane = x & 31;
    int rowidx = (b * Hn + y) * WPR;
    u32 c = mask[rowidx + w];
    u32 l = (w > 0) ? mask[rowidx + w - 1] : 0u;
    u32 r = (w < WPR - 1) ? mask[rowidx + w + 1] : 0u;
    u32 hd = c | (c >> 1) | (r << 31) | (c << 1) | (l >> 31);
    u32 up = (y > 0) ? mask[rowidx - WPR + w] : 0u;
    u32 dn = (y < Hn - 1) ? mask[rowidx + WPR + w] : 0u;
    u32 res = ((hd | up | dn) >> lane) & 1u;
    out[b * HW + y * Wn + x] = res ? 1.0f : 0.0f;
}

// ---------------- launch ----------------
extern "C" void kernel_launch(void* const* d_in, const int* in_sizes, int n_in,
                              void* d_out, int out_size) {
    const float* in = (const float*)d_in[0];
    float* out = (float*)d_out;

    void *pA, *pB, *pC, *pL, *pR, *pSA, *pSB, *pN;
    cudaGetSymbolAddress(&pA, g_mA);
    cudaGetSymbolAddress(&pB, g_mB);
    cudaGetSymbolAddress(&pC, g_mC);
    cudaGetSymbolAddress(&pL, g_L);
    cudaGetSymbolAddress(&pR, g_RL);
    cudaGetSymbolAddress(&pSA, g_SA);
    cudaGetSymbolAddress(&pSB, g_SB);
    cudaGetSymbolAddress(&pN, g_NC);
    u32* mA = (u32*)pA;
    u32* mB = (u32*)pB;
    u32* mC = (u32*)pC;
    int* L  = (int*)pL;
    int* RL = (int*)pR;
    int* SA = (int*)pSA;
    int* SB = (int*)pSB;
    int* NCa = (int*)pN;
    int* NCb = NCa + Bn;

    dim3 rg(Hn, Bn);                  // row kernels: block = one row
    const int WT = 256;
    const int WG = TOTW / WT;         // word kernels
    dim3 ob(32, 8);
    dim3 og(Wn / 32, Hn / 8, Bn);

    // threshold + CCL1 init
    k_thresh_init<<<rg, Wn>>>(in, mA, L, RL, SA, NCa);
    // CCL1 (foreground): merge, flatten
    k_merge<<<WG, WT>>>(mA, L, 0u);
    k_flatten<<<WG, WT>>>(mA, L, RL, SA, NCa, 0u);
    // RSO filter (guarded) + CCL2 (background) init
    k_filter_rso_init2<<<rg, Wn>>>(mA, L, RL, SA, SB, NCa, NCb, 2000);
    // CCL2: merge, flatten (inverted)
    k_merge<<<WG, WT>>>(mA, L, 0xffffffffu);
    k_flatten<<<WG, WT>>>(mA, L, RL, SB, NCb, 0xffffffffu);
    // fill holes < 301
    k_filter_holes<<<rg, Wn>>>(mA, L, SB, 301);

    // morphology: erode disk(2), open with disk(5)
    k_erode_r2<<<WG, WT>>>(mA, mB);
    k_erode_r5<<<WG, WT>>>(mB, mC);
    k_dilate_r5<<<WG, WT>>>(mC, mB);

    // CCL3 on opened mask
    k_init_mask<<<rg, Wn>>>(mB, L, RL, SA, NCa);
    k_merge<<<WG, WT>>>(mB, L, 0u);
    k_flatten<<<WG, WT>>>(mB, L, RL, SA, NCa, 0u);
    k_filter_rso<<<rg, Wn>>>(mB, L, SA, NCa, 2000);

    // dilate disk(1) + float output
    k_dilate1_out<<<og, ob>>>(mB, out);
}